// round 1
// baseline (speedup 1.0000x reference)
#include <cuda_runtime.h>
#include <cuda_bf16.h>
#include <cstdint>

#define N_NODES 10000
#define N_EDGES 640000
#define D 128

// Scratch: y = x @ W^T   (5.12 MB, __device__ global per allocation rules)
__device__ float g_y[N_NODES * D];

// ---------------------------------------------------------------------------
// Kernel 1: y = x @ W^T       (y[n][o] = sum_i x[n][i] * W[o][i])
// 256 threads/block, 32 rows/block. W tile transposed into smem (k-major),
// pad 132 keeps float4 compute reads 16B-aligned and conflict-free.
// ---------------------------------------------------------------------------
__global__ __launch_bounds__(256) void gemm_xWt_kernel(
    const float* __restrict__ x, const float* __restrict__ W,
    float* __restrict__ y)
{
    __shared__ float Wsh[64][132];   // [k][o]
    __shared__ float xsh[32][68];    // [r][k]

    const int tid  = threadIdx.x;
    const int row0 = blockIdx.x * 32;
    const int o0   = (tid & 31) * 4;    // output col base (warp lanes span o)
    const int r0   = (tid >> 5) * 4;    // row base (same for all lanes of a warp)

    float acc[4][4];
#pragma unroll
    for (int i = 0; i < 4; i++)
#pragma unroll
        for (int j = 0; j < 4; j++) acc[i][j] = 0.0f;

    for (int kt = 0; kt < D; kt += 64) {
        // Load W tile: W[o][kt+k] -> Wsh[k][o]; coalesced global reads.
        for (int t = tid; t < 64 * 128; t += 256) {
            int k = t & 63;
            int o = t >> 6;
            Wsh[k][o] = W[o * D + kt + k];
        }
        // Load x tile: x[row0+r][kt+k] -> xsh[r][k]; coalesced.
        for (int t = tid; t < 32 * 64; t += 256) {
            int k = t & 63;
            int r = t >> 6;
            int row = row0 + r;
            if (row >= N_NODES) row = N_NODES - 1;   // clamp (dead rows)
            xsh[r][k] = x[row * D + kt + k];
        }
        __syncthreads();

#pragma unroll 8
        for (int k = 0; k < 64; k++) {
            const float4 wv = *reinterpret_cast<const float4*>(&Wsh[k][o0]);
            float xv[4];
#pragma unroll
            for (int i = 0; i < 4; i++) xv[i] = xsh[r0 + i][k];
#pragma unroll
            for (int i = 0; i < 4; i++) {
                acc[i][0] = fmaf(xv[i], wv.x, acc[i][0]);
                acc[i][1] = fmaf(xv[i], wv.y, acc[i][1]);
                acc[i][2] = fmaf(xv[i], wv.z, acc[i][2]);
                acc[i][3] = fmaf(xv[i], wv.w, acc[i][3]);
            }
        }
        __syncthreads();
    }

#pragma unroll
    for (int i = 0; i < 4; i++) {
        int row = row0 + r0 + i;
        if (row < N_NODES) {
            float4 v = make_float4(acc[i][0], acc[i][1], acc[i][2], acc[i][3]);
            *reinterpret_cast<float4*>(&y[row * D + o0]) = v;
        }
    }
}

// ---------------------------------------------------------------------------
// Kernel 2: out[n][j] = b[j]     (bias broadcast init; overwrites poison)
// ---------------------------------------------------------------------------
__global__ __launch_bounds__(256) void init_bias_kernel(
    float* __restrict__ out, const float* __restrict__ b)
{
    int i = blockIdx.x * blockDim.x + threadIdx.x;   // 1,280,000 threads
    if (i < N_NODES * D) out[i] = b[i & (D - 1)];
}

// ---------------------------------------------------------------------------
// Kernel 3: scatter-add  out[dst[e]] += y[src[e]]   (warp per edge)
// lane l handles float4 chunk l (32 * 16B = 128 floats). red.global.add.v4
// quarters the atomic op count vs scalar atomicAdd.
// ---------------------------------------------------------------------------
__global__ __launch_bounds__(256) void scatter_kernel(
    const float4* __restrict__ y4, const int* __restrict__ src,
    const int* __restrict__ dst, float* __restrict__ out)
{
    const int gtid = blockIdx.x * blockDim.x + threadIdx.x;
    const int e    = gtid >> 5;
    const int lane = gtid & 31;
    if (e >= N_EDGES) return;

    const int s = __ldg(&src[e]);
    const int d = __ldg(&dst[e]);

    const float4 v = y4[s * (D / 4) + lane];
    float* p = out + (size_t)d * D + lane * 4;
    asm volatile("red.global.add.v4.f32 [%0], {%1,%2,%3,%4};"
                 :: "l"(p), "f"(v.x), "f"(v.y), "f"(v.z), "f"(v.w)
                 : "memory");
}

// ---------------------------------------------------------------------------
extern "C" void kernel_launch(void* const* d_in, const int* in_sizes, int n_in,
                              void* d_out, int out_size)
{
    const float* x   = (const float*)d_in[0];   // [10000,128]
    const int*   src = (const int*)  d_in[1];   // [640000]
    const int*   dst = (const int*)  d_in[2];   // [640000]
    const float* W   = (const float*)d_in[3];   // [128,128]
    const float* b   = (const float*)d_in[4];   // [128]
    float*       out = (float*)d_out;           // [10000,128]

    float* y;
    cudaGetSymbolAddress((void**)&y, g_y);

    // y = x @ W^T
    gemm_xWt_kernel<<<(N_NODES + 31) / 32, 256>>>(x, W, y);

    // out = b (broadcast)
    init_bias_kernel<<<(N_NODES * D + 255) / 256, 256>>>(out, b);

    // out[dst] += y[src]
    const long long total_threads = (long long)N_EDGES * 32;
    scatter_kernel<<<(int)((total_threads + 255) / 256), 256>>>(
        (const float4*)y, src, dst, out);
}